// round 1
// baseline (speedup 1.0000x reference)
#include <cuda_runtime.h>
#include <math.h>

// Model dims
#define BB   1024
#define TT   20
#define CC   512
#define HH   8
#define LL   8
#define DD   64
#define MTOK (BB * TT)   // 20480 tokens

// ---------------------------------------------------------------------------
// Scratch (device globals: no allocation allowed in kernel_launch)
// ---------------------------------------------------------------------------
__device__ float g_h  [MTOK * CC];        // residual stream          (~42 MB)
__device__ float g_xn [MTOK * CC];        // layernorm output         (~42 MB)
__device__ float g_qkv[MTOK * 3 * CC];    // qkv projections          (~126 MB)
__device__ float g_y  [MTOK * CC];        // attention output         (~42 MB)
__device__ float g_mid[MTOK * 4 * CC];    // MLP hidden               (~168 MB)

// ---------------------------------------------------------------------------
// Encoder: h = x @ enc_w + enc_b + wpe[t+1]   (V = 2, unrolled)
// ---------------------------------------------------------------------------
__global__ void encode_kernel(const float* __restrict__ x,
                              const float* __restrict__ enc_w,
                              const float* __restrict__ enc_b,
                              const float* __restrict__ wpe,
                              float* __restrict__ out) {
    int i = blockIdx.x * blockDim.x + threadIdx.x;
    if (i >= MTOK * CC) return;
    int m = i / CC, c = i % CC;
    int t = m % TT;
    float x0 = x[m * 2 + 0], x1 = x[m * 2 + 1];
    out[i] = x0 * enc_w[c] + x1 * enc_w[CC + c] + enc_b[c] + wpe[(t + 1) * CC + c];
}

// ---------------------------------------------------------------------------
// LayerNorm: one 128-thread block per token row (C = 512 -> 4 elems/thread)
// ---------------------------------------------------------------------------
__global__ void ln_kernel(const float* __restrict__ in,
                          const float* __restrict__ w,
                          const float* __restrict__ b,
                          float* __restrict__ out) {
    int row = blockIdx.x;
    const float* p = in + (size_t)row * CC;
    float v[4];
    float s = 0.f, sq = 0.f;
#pragma unroll
    for (int i = 0; i < 4; i++) {
        v[i] = p[threadIdx.x + i * 128];
        s  += v[i];
        sq += v[i] * v[i];
    }
#pragma unroll
    for (int o = 16; o > 0; o >>= 1) {
        s  += __shfl_xor_sync(0xffffffff, s, o);
        sq += __shfl_xor_sync(0xffffffff, sq, o);
    }
    __shared__ float red[8];
    int warp = threadIdx.x >> 5;
    if ((threadIdx.x & 31) == 0) { red[warp] = s; red[4 + warp] = sq; }
    __syncthreads();
    s  = red[0] + red[1] + red[2] + red[3];
    sq = red[4] + red[5] + red[6] + red[7];
    float mu  = s / CC;
    float var = sq / CC - mu * mu;
    float inv = rsqrtf(var + 1e-5f);
    float* q = out + (size_t)row * CC;
#pragma unroll
    for (int i = 0; i < 4; i++) {
        int c = threadIdx.x + i * 128;
        q[c] = (v[i] - mu) * inv * w[c] + b[c];
    }
}

// ---------------------------------------------------------------------------
// SGEMM 128x128x8, 256 threads, 8x8 per thread. Row-major A[M,K], W[K,N].
// EPI: 0 = +bias, 1 = +bias then exact GELU, 2 = +bias then += residual
// M % 128 == 0, N % 128 == 0, K % 8 == 0 (holds for all call sites).
// ---------------------------------------------------------------------------
template <int EPI>
__global__ void sgemm_kernel(const float* __restrict__ A,
                             const float* __restrict__ W,
                             const float* __restrict__ bias,
                             const float* __restrict__ res,
                             float* __restrict__ out,
                             int Ndim, int Kdim) {
    __shared__ float As[8][128];
    __shared__ float Bs[8][128];
    int bm = blockIdx.y * 128, bn = blockIdx.x * 128;
    int tid = threadIdx.x;           // 0..255
    int tx = tid % 16, ty = tid / 16;

    float acc[8][8] = {};

    int arow  = tid / 2;             // 0..127
    int acol4 = (tid % 2) * 4;       // 0 or 4
    int brow  = tid / 32;            // 0..7
    int bcol4 = (tid % 32) * 4;      // 0..124

    const float* Ap = A + (size_t)(bm + arow) * Kdim + acol4;
    const float* Wp = W + (size_t)brow * Ndim + bn + bcol4;

    for (int k0 = 0; k0 < Kdim; k0 += 8) {
        float4 av = *(const float4*)(Ap + k0);
        As[acol4 + 0][arow] = av.x;
        As[acol4 + 1][arow] = av.y;
        As[acol4 + 2][arow] = av.z;
        As[acol4 + 3][arow] = av.w;
        *(float4*)&Bs[brow][bcol4] = *(const float4*)(Wp + (size_t)k0 * Ndim);
        __syncthreads();
#pragma unroll
        for (int k = 0; k < 8; k++) {
            float4 a0 = *(const float4*)&As[k][ty * 8];
            float4 a1 = *(const float4*)&As[k][ty * 8 + 4];
            float4 b0 = *(const float4*)&Bs[k][tx * 8];
            float4 b1 = *(const float4*)&Bs[k][tx * 8 + 4];
            float a[8] = {a0.x, a0.y, a0.z, a0.w, a1.x, a1.y, a1.z, a1.w};
            float bb[8] = {b0.x, b0.y, b0.z, b0.w, b1.x, b1.y, b1.z, b1.w};
#pragma unroll
            for (int i = 0; i < 8; i++)
#pragma unroll
                for (int j = 0; j < 8; j++)
                    acc[i][j] += a[i] * bb[j];
        }
        __syncthreads();
    }

#pragma unroll
    for (int i = 0; i < 8; i++) {
        int row = bm + ty * 8 + i;
        float* op = out + (size_t)row * Ndim + bn;
        const float* rp = (EPI == 2) ? (res + (size_t)row * Ndim + bn) : nullptr;
#pragma unroll
        for (int j = 0; j < 8; j++) {
            int col = tx * 8 + j;
            float vv = acc[i][j] + bias[bn + col];
            if (EPI == 1) vv = 0.5f * vv * (1.0f + erff(vv * 0.70710678118654752440f));
            if (EPI == 2) vv += rp[col];
            op[col] = vv;
        }
    }
}

// ---------------------------------------------------------------------------
// Attention: one 128-thread block per (batch, head). T=20, D=64 in smem.
// ---------------------------------------------------------------------------
__global__ void attn_kernel(const float* __restrict__ qkv, float* __restrict__ y) {
    __shared__ float Q[TT][DD], K[TT][DD], V[TT][DD], S[TT][TT + 1];
    int b = blockIdx.x / HH, h = blockIdx.x % HH;
    const float* base = qkv + (size_t)b * TT * 3 * CC + h * DD;

    for (int idx = threadIdx.x; idx < TT * DD; idx += blockDim.x) {
        int t = idx / DD, d = idx % DD;
        const float* p = base + (size_t)t * 3 * CC + d;
        Q[t][d] = p[0];
        K[t][d] = p[CC];
        V[t][d] = p[2 * CC];
    }
    __syncthreads();

    const float scale = 0.125f;  // 1/sqrt(64)
    for (int idx = threadIdx.x; idx < TT * TT; idx += blockDim.x) {
        int tq = idx / TT, tk = idx % TT;
        if (tk <= tq) {
            float s = 0.f;
#pragma unroll
            for (int d = 0; d < DD; d++) s += Q[tq][d] * K[tk][d];
            S[tq][tk] = s * scale;
        }
    }
    __syncthreads();

    if (threadIdx.x < TT) {
        int tq = threadIdx.x;
        float mx = -1e30f;
        for (int tk = 0; tk <= tq; tk++) mx = fmaxf(mx, S[tq][tk]);
        float sum = 0.f;
        for (int tk = 0; tk <= tq; tk++) {
            float e = expf(S[tq][tk] - mx);
            S[tq][tk] = e;
            sum += e;
        }
        float inv = 1.f / sum;
        for (int tk = 0; tk <= tq; tk++) S[tq][tk] *= inv;
    }
    __syncthreads();

    for (int idx = threadIdx.x; idx < TT * DD; idx += blockDim.x) {
        int t = idx / DD, d = idx % DD;
        float o = 0.f;
        for (int tk = 0; tk <= t; tk++) o += S[t][tk] * V[tk][d];
        y[((size_t)b * TT + t) * CC + h * DD + d] = o;
    }
}

// ---------------------------------------------------------------------------
// Predictor: out[m, v] = xn[m,:] . pred_w[:, v] + pred_b[v], V = 2.
// One warp per token.
// ---------------------------------------------------------------------------
__global__ void pred_kernel(const float* __restrict__ xn,
                            const float* __restrict__ pw,
                            const float* __restrict__ pb,
                            float* __restrict__ out) {
    int m = blockIdx.x * 4 + (threadIdx.x >> 5);
    int lane = threadIdx.x & 31;
    const float* p = xn + (size_t)m * CC;
    float a0 = 0.f, a1 = 0.f;
    for (int c = lane; c < CC; c += 32) {
        float v = p[c];
        a0 += v * pw[c * 2 + 0];
        a1 += v * pw[c * 2 + 1];
    }
#pragma unroll
    for (int o = 16; o > 0; o >>= 1) {
        a0 += __shfl_xor_sync(0xffffffff, a0, o);
        a1 += __shfl_xor_sync(0xffffffff, a1, o);
    }
    if (lane == 0) {
        out[m * 2 + 0] = a0 + pb[0];
        out[m * 2 + 1] = a1 + pb[1];
    }
}

// ---------------------------------------------------------------------------
// Launch
// ---------------------------------------------------------------------------
extern "C" void kernel_launch(void* const* d_in, const int* in_sizes, int n_in,
                              void* d_out, int out_size) {
    const float* x      = (const float*)d_in[0];
    const float* enc_w  = (const float*)d_in[1];
    const float* enc_b  = (const float*)d_in[2];
    const float* wpe    = (const float*)d_in[3];
    const float* ln1_w  = (const float*)d_in[4];
    const float* ln1_b  = (const float*)d_in[5];
    const float* attn_w = (const float*)d_in[6];
    const float* attn_b = (const float*)d_in[7];
    const float* proj_w = (const float*)d_in[8];
    const float* proj_b = (const float*)d_in[9];
    const float* ln2_w  = (const float*)d_in[10];
    const float* ln2_b  = (const float*)d_in[11];
    const float* fc1_w  = (const float*)d_in[12];
    const float* fc1_b  = (const float*)d_in[13];
    const float* fc2_w  = (const float*)d_in[14];
    const float* fc2_b  = (const float*)d_in[15];
    const float* lnf_w  = (const float*)d_in[16];
    const float* lnf_b  = (const float*)d_in[17];
    const float* pred_w = (const float*)d_in[18];
    const float* pred_b = (const float*)d_in[19];

    float *h, *xn, *qkv, *y, *mid;
    cudaGetSymbolAddress((void**)&h,   g_h);
    cudaGetSymbolAddress((void**)&xn,  g_xn);
    cudaGetSymbolAddress((void**)&qkv, g_qkv);
    cudaGetSymbolAddress((void**)&y,   g_y);
    cudaGetSymbolAddress((void**)&mid, g_mid);

    encode_kernel<<<(MTOK * CC + 255) / 256, 256>>>(x, enc_w, enc_b, wpe, h);

    dim3 gQKV(3 * CC / 128, MTOK / 128);   // 12 x 160
    dim3 gC  (CC / 128,     MTOK / 128);   //  4 x 160
    dim3 gFC1(4 * CC / 128, MTOK / 128);   // 16 x 160

    for (int l = 0; l < LL; l++) {
        ln_kernel<<<MTOK, 128>>>(h, ln1_w + l * CC, ln1_b + l * CC, xn);
        sgemm_kernel<0><<<gQKV, 256>>>(xn, attn_w + (size_t)l * CC * 3 * CC,
                                       attn_b + (size_t)l * 3 * CC, nullptr, qkv,
                                       3 * CC, CC);
        attn_kernel<<<BB * HH, 128>>>(qkv, y);
        sgemm_kernel<2><<<gC, 256>>>(y, proj_w + (size_t)l * CC * CC,
                                     proj_b + (size_t)l * CC, h, h, CC, CC);
        ln_kernel<<<MTOK, 128>>>(h, ln2_w + l * CC, ln2_b + l * CC, xn);
        sgemm_kernel<1><<<gFC1, 256>>>(xn, fc1_w + (size_t)l * CC * 4 * CC,
                                       fc1_b + (size_t)l * 4 * CC, nullptr, mid,
                                       4 * CC, CC);
        sgemm_kernel<2><<<gC, 256>>>(mid, fc2_w + (size_t)l * 4 * CC * CC,
                                     fc2_b + (size_t)l * CC, h, h, CC, 4 * CC);
    }

    ln_kernel<<<MTOK, 128>>>(h, lnf_w, lnf_b, xn);
    pred_kernel<<<MTOK / 4, 128>>>(xn, pred_w, pred_b, (float*)d_out);
}

// round 3
// speedup vs baseline: 2.1410x; 2.1410x over previous
#include <cuda_runtime.h>
#include <math.h>

// Model dims
#define BB   1024
#define TT   20
#define CC   512
#define HH   8
#define LL   8
#define DD   64
#define MTOK (BB * TT)   // 20480 tokens

// ---------------------------------------------------------------------------
// Scratch (device globals: no allocation allowed in kernel_launch)
// ---------------------------------------------------------------------------
__device__ float g_h  [MTOK * CC];
__device__ float g_xn [MTOK * CC];
__device__ float g_qkv[MTOK * 3 * CC];
__device__ float g_y  [MTOK * CC];
__device__ float g_mid[MTOK * 4 * CC];

__device__ __forceinline__ unsigned f2tf32(float f) {
    unsigned r;
    asm("cvt.rna.tf32.f32 %0, %1;" : "=r"(r) : "f"(f));
    return r;
}

// ---------------------------------------------------------------------------
// Encoder: h = x @ enc_w + enc_b + wpe[t+1]   (V = 2, unrolled)
// ---------------------------------------------------------------------------
__global__ void encode_kernel(const float* __restrict__ x,
                              const float* __restrict__ enc_w,
                              const float* __restrict__ enc_b,
                              const float* __restrict__ wpe,
                              float* __restrict__ out) {
    int i = blockIdx.x * blockDim.x + threadIdx.x;
    if (i >= MTOK * CC) return;
    int m = i / CC, c = i % CC;
    int t = m % TT;
    float x0 = x[m * 2 + 0], x1 = x[m * 2 + 1];
    out[i] = x0 * enc_w[c] + x1 * enc_w[CC + c] + enc_b[c] + wpe[(t + 1) * CC + c];
}

// ---------------------------------------------------------------------------
// LayerNorm: one 128-thread block per token row
// ---------------------------------------------------------------------------
__global__ void ln_kernel(const float* __restrict__ in,
                          const float* __restrict__ w,
                          const float* __restrict__ b,
                          float* __restrict__ out) {
    int row = blockIdx.x;
    const float* p = in + (size_t)row * CC;
    float v[4];
    float s = 0.f, sq = 0.f;
#pragma unroll
    for (int i = 0; i < 4; i++) {
        v[i] = p[threadIdx.x + i * 128];
        s  += v[i];
        sq += v[i] * v[i];
    }
#pragma unroll
    for (int o = 16; o > 0; o >>= 1) {
        s  += __shfl_xor_sync(0xffffffff, s, o);
        sq += __shfl_xor_sync(0xffffffff, sq, o);
    }
    __shared__ float red[8];
    int warp = threadIdx.x >> 5;
    if ((threadIdx.x & 31) == 0) { red[warp] = s; red[4 + warp] = sq; }
    __syncthreads();
    s  = red[0] + red[1] + red[2] + red[3];
    sq = red[4] + red[5] + red[6] + red[7];
    float mu  = s / CC;
    float var = sq / CC - mu * mu;
    float inv = rsqrtf(var + 1e-5f);
    float* q = out + (size_t)row * CC;
#pragma unroll
    for (int i = 0; i < 4; i++) {
        int c = threadIdx.x + i * 128;
        q[c] = (v[i] - mu) * inv * w[c] + b[c];
    }
}

// ---------------------------------------------------------------------------
// TF32 tensor-core GEMM: 128x128 CTA tile, K-tile 32, 256 threads (8 warps,
// 2x4 layout, 64x32 warp tile, m16n8k8 tf32 mma.sync).
// A[M,K] row-major, W[K,N] row-major. M%128==0, N%128==0, K%32==0.
// EPI: 0 = +bias, 1 = +bias,GELU(exact), 2 = +bias,+residual
// ---------------------------------------------------------------------------
#define KT   32
#define SPAD 136   // row pitch in floats: 136 % 32 == 8 -> conflict-free frags

template <int EPI>
__global__ void __launch_bounds__(256, 2)
tgemm_kernel(const float* __restrict__ A,
             const float* __restrict__ W,
             const float* __restrict__ bias,
             const float* __restrict__ res,
             float* __restrict__ out,
             int Ndim, int Kdim) {
    __shared__ float As[KT][SPAD];   // k-major (transposed A tile)
    __shared__ float Bs[KT][SPAD];   // k-major (natural W tile)

    const int bm = blockIdx.y * 128, bn = blockIdx.x * 128;
    const int tid  = threadIdx.x;
    const int lane = tid & 31;
    const int wid  = tid >> 5;
    const int g    = lane >> 2;      // groupID 0..7
    const int tig  = lane & 3;       // thread-in-group 0..3
    const int warp_m = (wid >> 2) * 64;   // 0 or 64
    const int warp_n = (wid & 3) * 32;    // 0,32,64,96

    float acc[4][4][4];
#pragma unroll
    for (int mi = 0; mi < 4; mi++)
#pragma unroll
        for (int ni = 0; ni < 4; ni++)
#pragma unroll
            for (int r = 0; r < 4; r++) acc[mi][ni][r] = 0.f;

    // A load mapping: each thread loads row (tid&127), cols c0+8i (4x float4)
    const int a_row = tid & 127;
    const int a_c0  = (tid >> 7) * 4;
    // B load mapping: each thread loads col n4, rows b_k+8i (4x float4)
    const int b_n4 = (tid & 31) * 4;
    const int b_k  = tid >> 5;

    const float* Abase = A + (size_t)(bm + a_row) * Kdim + a_c0;
    const float* Wbase = W + (size_t)b_k * Ndim + bn + b_n4;

    for (int k0 = 0; k0 < Kdim; k0 += KT) {
        // ---- fill smem (with tf32 rounding) ----
#pragma unroll
        for (int i = 0; i < 4; i++) {
            float4 av = *(const float4*)(Abase + k0 + 8 * i);
            int kc = a_c0 + 8 * i;
            As[kc + 0][a_row] = __uint_as_float(f2tf32(av.x));
            As[kc + 1][a_row] = __uint_as_float(f2tf32(av.y));
            As[kc + 2][a_row] = __uint_as_float(f2tf32(av.z));
            As[kc + 3][a_row] = __uint_as_float(f2tf32(av.w));
        }
#pragma unroll
        for (int i = 0; i < 4; i++) {
            float4 bv = *(const float4*)(Wbase + (size_t)(k0 + 8 * i) * Ndim);
            float4 cv;
            cv.x = __uint_as_float(f2tf32(bv.x));
            cv.y = __uint_as_float(f2tf32(bv.y));
            cv.z = __uint_as_float(f2tf32(bv.z));
            cv.w = __uint_as_float(f2tf32(bv.w));
            *(float4*)&Bs[b_k + 8 * i][b_n4] = cv;
        }
        __syncthreads();

        // ---- compute: 4 k-steps of 8 ----
#pragma unroll
        for (int ks = 0; ks < 4; ks++) {
            const int kr0 = ks * 8 + tig;
            const int kr1 = kr0 + 4;
            unsigned a[4][4], b[4][2];
#pragma unroll
            for (int mi = 0; mi < 4; mi++) {
                int m0 = warp_m + 16 * mi;
                a[mi][0] = __float_as_uint(As[kr0][m0 + g]);
                a[mi][1] = __float_as_uint(As[kr0][m0 + g + 8]);
                a[mi][2] = __float_as_uint(As[kr1][m0 + g]);
                a[mi][3] = __float_as_uint(As[kr1][m0 + g + 8]);
            }
#pragma unroll
            for (int ni = 0; ni < 4; ni++) {
                int n0 = warp_n + 8 * ni;
                b[ni][0] = __float_as_uint(Bs[kr0][n0 + g]);
                b[ni][1] = __float_as_uint(Bs[kr1][n0 + g]);
            }
#pragma unroll
            for (int mi = 0; mi < 4; mi++)
#pragma unroll
                for (int ni = 0; ni < 4; ni++) {
                    asm volatile(
                        "mma.sync.aligned.m16n8k8.row.col.f32.tf32.tf32.f32 "
                        "{%0,%1,%2,%3}, {%4,%5,%6,%7}, {%8,%9}, {%0,%1,%2,%3};"
                        : "+f"(acc[mi][ni][0]), "+f"(acc[mi][ni][1]),
                          "+f"(acc[mi][ni][2]), "+f"(acc[mi][ni][3])
                        : "r"(a[mi][0]), "r"(a[mi][1]), "r"(a[mi][2]), "r"(a[mi][3]),
                          "r"(b[ni][0]), "r"(b[ni][1]));
                }
        }
        __syncthreads();
    }

    // ---- epilogue ----
#pragma unroll
    for (int mi = 0; mi < 4; mi++) {
#pragma unroll
        for (int half = 0; half < 2; half++) {
            int row = bm + warp_m + 16 * mi + g + 8 * half;
            float* op = out + (size_t)row * Ndim + bn;
            const float* rp = (EPI == 2) ? (res + (size_t)row * Ndim + bn) : nullptr;
#pragma unroll
            for (int ni = 0; ni < 4; ni++) {
                int col = warp_n + 8 * ni + 2 * tig;
#pragma unroll
                for (int c = 0; c < 2; c++) {
                    float vv = acc[mi][ni][2 * half + c] + bias[bn + col + c];
                    if (EPI == 1) vv = 0.5f * vv * (1.0f + erff(vv * 0.70710678118654752440f));
                    if (EPI == 2) vv += rp[col + c];
                    op[col + c] = vv;
                }
            }
        }
    }
}

// ---------------------------------------------------------------------------
// Attention: one 128-thread block per (batch, head). T=20, D=64 in smem.
// ---------------------------------------------------------------------------
__global__ void attn_kernel(const float* __restrict__ qkv, float* __restrict__ y) {
    __shared__ float Q[TT][DD], K[TT][DD], V[TT][DD], S[TT][TT + 1];
    int b = blockIdx.x / HH, h = blockIdx.x % HH;
    const float* base = qkv + (size_t)b * TT * 3 * CC + h * DD;

    for (int idx = threadIdx.x; idx < TT * DD; idx += blockDim.x) {
        int t = idx / DD, d = idx % DD;
        const float* p = base + (size_t)t * 3 * CC + d;
        Q[t][d] = p[0];
        K[t][d] = p[CC];
        V[t][d] = p[2 * CC];
    }
    __syncthreads();

    const float scale = 0.125f;
    for (int idx = threadIdx.x; idx < TT * TT; idx += blockDim.x) {
        int tq = idx / TT, tk = idx % TT;
        if (tk <= tq) {
            float s = 0.f;
#pragma unroll
            for (int d = 0; d < DD; d++) s += Q[tq][d] * K[tk][d];
            S[tq][tk] = s * scale;
        }
    }
    __syncthreads();

    if (threadIdx.x < TT) {
        int tq = threadIdx.x;
        float mx = -1e30f;
        for (int tk = 0; tk <= tq; tk++) mx = fmaxf(mx, S[tq][tk]);
        float sum = 0.f;
        for (int tk = 0; tk <= tq; tk++) {
            float e = expf(S[tq][tk] - mx);
            S[tq][tk] = e;
            sum += e;
        }
        float inv = 1.f / sum;
        for (int tk = 0; tk <= tq; tk++) S[tq][tk] *= inv;
    }
    __syncthreads();

    for (int idx = threadIdx.x; idx < TT * DD; idx += blockDim.x) {
        int t = idx / DD, d = idx % DD;
        float o = 0.f;
        for (int tk = 0; tk <= t; tk++) o += S[t][tk] * V[tk][d];
        y[((size_t)b * TT + t) * CC + h * DD + d] = o;
    }
}

// ---------------------------------------------------------------------------
// Predictor: out[m, v] = xn[m,:] . pred_w[:, v] + pred_b[v], V = 2.
// ---------------------------------------------------------------------------
__global__ void pred_kernel(const float* __restrict__ xn,
                            const float* __restrict__ pw,
                            const float* __restrict__ pb,
                            float* __restrict__ out) {
    int m = blockIdx.x * 4 + (threadIdx.x >> 5);
    int lane = threadIdx.x & 31;
    const float* p = xn + (size_t)m * CC;
    float a0 = 0.f, a1 = 0.f;
    for (int c = lane; c < CC; c += 32) {
        float v = p[c];
        a0 += v * pw[c * 2 + 0];
        a1 += v * pw[c * 2 + 1];
    }
#pragma unroll
    for (int o = 16; o > 0; o >>= 1) {
        a0 += __shfl_xor_sync(0xffffffff, a0, o);
        a1 += __shfl_xor_sync(0xffffffff, a1, o);
    }
    if (lane == 0) {
        out[m * 2 + 0] = a0 + pb[0];
        out[m * 2 + 1] = a1 + pb[1];
    }
}

// ---------------------------------------------------------------------------
// Launch
// ---------------------------------------------------------------------------
extern "C" void kernel_launch(void* const* d_in, const int* in_sizes, int n_in,
                              void* d_out, int out_size) {
    const float* x      = (const float*)d_in[0];
    const float* enc_w  = (const float*)d_in[1];
    const float* enc_b  = (const float*)d_in[2];
    const float* wpe    = (const float*)d_in[3];
    const float* ln1_w  = (const float*)d_in[4];
    const float* ln1_b  = (const float*)d_in[5];
    const float* attn_w = (const float*)d_in[6];
    const float* attn_b = (const float*)d_in[7];
    const float* proj_w = (const float*)d_in[8];
    const float* proj_b = (const float*)d_in[9];
    const float* ln2_w  = (const float*)d_in[10];
    const float* ln2_b  = (const float*)d_in[11];
    const float* fc1_w  = (const float*)d_in[12];
    const float* fc1_b  = (const float*)d_in[13];
    const float* fc2_w  = (const float*)d_in[14];
    const float* fc2_b  = (const float*)d_in[15];
    const float* lnf_w  = (const float*)d_in[16];
    const float* lnf_b  = (const float*)d_in[17];
    const float* pred_w = (const float*)d_in[18];
    const float* pred_b = (const float*)d_in[19];

    float *h, *xn, *qkv, *y, *mid;
    cudaGetSymbolAddress((void**)&h,   g_h);
    cudaGetSymbolAddress((void**)&xn,  g_xn);
    cudaGetSymbolAddress((void**)&qkv, g_qkv);
    cudaGetSymbolAddress((void**)&y,   g_y);
    cudaGetSymbolAddress((void**)&mid, g_mid);

    encode_kernel<<<(MTOK * CC + 255) / 256, 256>>>(x, enc_w, enc_b, wpe, h);

    dim3 gQKV(3 * CC / 128, MTOK / 128);   // 12 x 160
    dim3 gC  (CC / 128,     MTOK / 128);   //  4 x 160
    dim3 gFC1(4 * CC / 128, MTOK / 128);   // 16 x 160

    for (int l = 0; l < LL; l++) {
        ln_kernel<<<MTOK, 128>>>(h, ln1_w + l * CC, ln1_b + l * CC, xn);
        tgemm_kernel<0><<<gQKV, 256>>>(xn, attn_w + (size_t)l * CC * 3 * CC,
                                       attn_b + (size_t)l * 3 * CC, nullptr, qkv,
                                       3 * CC, CC);
        attn_kernel<<<BB * HH, 128>>>(qkv, y);
        tgemm_kernel<2><<<gC, 256>>>(y, proj_w + (size_t)l * CC * CC,
                                     proj_b + (size_t)l * CC, h, h, CC, CC);
        ln_kernel<<<MTOK, 128>>>(h, ln2_w + l * CC, ln2_b + l * CC, xn);
        tgemm_kernel<1><<<gFC1, 256>>>(xn, fc1_w + (size_t)l * CC * 4 * CC,
                                       fc1_b + (size_t)l * 4 * CC, nullptr, mid,
                                       4 * CC, CC);
        tgemm_kernel<2><<<gC, 256>>>(mid, fc2_w + (size_t)l * 4 * CC * CC,
                                     fc2_b + (size_t)l * CC, h, h, CC, 4 * CC);
    }

    ln_kernel<<<MTOK, 128>>>(h, lnf_w, lnf_b, xn);
    pred_kernel<<<MTOK / 4, 128>>>(xn, pred_w, pred_b, (float*)d_out);
}